// round 13
// baseline (speedup 1.0000x reference)
#include <cuda_runtime.h>
#include <cuda_bf16.h>
#include <cstdint>

#define Bsz 1024
#define Nn  256
#define Dd  64
#define LAT 128
#define EC  32
#define NTHREADS 512

// Row strides (bytes): 64 bf16 + 16B pad = 144 (bank step 4/row -> CF ldmatrix);
// 32 bf16 + 16B pad = 80 (bank step 20/row -> CF).
#define SA 144
#define SE 80

// SMEM byte offsets — pure bf16, ~97KB, 1 CTA/SM (regs bound at 16 warps anyway)
#define OFF_A    0u        // A  [256][144] = 36864
#define OFF_WF   36864u    // Wf [128][144] = 18432
#define OFF_WC   55296u    // Wc [32][144]  = 4608
#define OFF_WA   59904u    // Wa2[128][80]  = 10240 (pre-scaled by log2e)
#define OFF_E    70144u    // E' [256][80]  = 20480
#define OFF_BC   90624u    // 32 f32
#define OFF_BFB  90752u    // 128 f32
#define OFF_REDS 91264u    // 4*132 f32
#define OFF_REDW 93376u    // 4*132 f32
#define OFF_AGG  95488u    // 128 f32
#define OFF_P4   96000u    // 4*132 f32
#define SMEM_TOTAL 98112u

__device__ __forceinline__ uint32_t smem_u32(const void* p) {
    uint32_t a;
    asm("{ .reg .u64 t; cvta.to.shared.u64 t, %1; cvt.u32.u64 %0, t; }" : "=r"(a) : "l"(p));
    return a;
}
__device__ __forceinline__ void ldsm4(uint32_t& r0, uint32_t& r1, uint32_t& r2,
                                      uint32_t& r3, uint32_t addr) {
    asm volatile("ldmatrix.sync.aligned.m8n8.x4.shared.b16 {%0,%1,%2,%3}, [%4];"
                 : "=r"(r0), "=r"(r1), "=r"(r2), "=r"(r3) : "r"(addr));
}
__device__ __forceinline__ void mma_bf16(float d[4], uint32_t a0, uint32_t a1,
                                         uint32_t a2, uint32_t a3,
                                         uint32_t b0, uint32_t b1) {
    asm volatile(
        "mma.sync.aligned.m16n8k16.row.col.f32.bf16.bf16.f32 "
        "{%0,%1,%2,%3}, {%4,%5,%6,%7}, {%8,%9}, {%0,%1,%2,%3};"
        : "+f"(d[0]), "+f"(d[1]), "+f"(d[2]), "+f"(d[3])
        : "r"(a0), "r"(a1), "r"(a2), "r"(a3), "r"(b0), "r"(b1));
}
__device__ __forceinline__ uint32_t cvt2(float v0, float v1) {
    __nv_bfloat162 h2 = __float22bfloat162_rn(make_float2(v0, v1));
    return *reinterpret_cast<uint32_t*>(&h2);
}
__device__ __forceinline__ float ex2(float x) {
    float r;
    asm("ex2.approx.f32 %0, %1;" : "=f"(r) : "f"(x));
    return r;
}

extern __shared__ __align__(1024) char smem[];

__global__ void __launch_bounds__(NTHREADS, 1)
arm_mma12_kernel(const float* __restrict__ nb, const float* __restrict__ Wc,
                 const float* __restrict__ bc, const float* __restrict__ Wf,
                 const float* __restrict__ bf, const float* __restrict__ Wa,
                 const float* __restrict__ Wl, const float* __restrict__ bl,
                 float* __restrict__ out)
{
    const uint32_t sbase = smem_u32(smem);
    const int t = threadIdx.x;
    const int lane = t & 31, warp = t >> 5;   // 16 warps

    // ---------------- Stage bf16 weights ONCE per CTA ----------------
    {
        const float LOG2E = 1.4426950408889634f;
        #pragma unroll
        for (int it = 0; it < 8; ++it) {              // Wf^T: 128n x 32 d-pairs
            int idx = it * NTHREADS + t;
            int n = idx & 127, d0 = (idx >> 7) * 2;
            *(uint32_t*)(smem + OFF_WF + n * SA + d0 * 2) =
                cvt2(Wf[d0 * LAT + n], Wf[(d0 + 1) * LAT + n]);
        }
        #pragma unroll
        for (int it = 0; it < 2; ++it) {              // Wc^T: 32e x 32 d-pairs
            int idx = it * NTHREADS + t;
            int e = idx & 31, d0 = (idx >> 5) * 2;
            *(uint32_t*)(smem + OFF_WC + e * SA + d0 * 2) =
                cvt2(Wc[d0 * EC + e], Wc[(d0 + 1) * EC + e]);
        }
        #pragma unroll
        for (int it = 0; it < 4; ++it) {              // Wa2^T * log2e: 128n x 16 e-pairs
            int idx = it * NTHREADS + t;
            int n = idx & 127, e0 = (idx >> 7) * 2;
            *(uint32_t*)(smem + OFF_WA + n * SE + e0 * 2) =
                cvt2(LOG2E * Wa[(EC + e0) * LAT + n],
                     LOG2E * Wa[(EC + e0 + 1) * LAT + n]);
        }
        if (t < EC)  ((float*)(smem + OFF_BC))[t]  = bc[t];
        if (t < LAT) ((float*)(smem + OFF_BFB))[t] = bf[t];
    }
    __syncthreads();

    // ---------------- Fragment lane constants ----------------
    const int matA = lane >> 3;
    const int arow = (lane & 7) + ((matA & 1) << 3);
    const int acolB = ((matA >> 1) << 3) * 2;          // byte offset
    const int brow = ((lane >> 4) << 3) + (lane & 7);
    const int bcolB = (((lane >> 3) & 1) << 3) * 2;
    const int rquad = lane >> 2, cpair = (lane & 3) * 2;
    const int mg = warp >> 2, n0 = (warp & 3) * 32;    // L/F grid: 4x4, 64-row blocks
    const int emg = warp;                              // E grid: 16 x 16-row tiles

    float* sbc  = (float*)(smem + OFF_BC);
    float* sbfb = (float*)(smem + OFF_BFB);
    float* sRedS = (float*)(smem + OFF_REDS);
    float* sRedW = (float*)(smem + OFF_REDW);
    float* sAgg = (float*)(smem + OFF_AGG);
    float* sP4  = (float*)(smem + OFF_P4);

    // Per-fragment column biases (for accumulator init)
    const float bcI0 = sbc[cpair],  bcI1 = sbc[cpair + 1];   // used with nt offset below

    // ---- Hoist B_F (Wf^T cols n0..n0+31, K=64) fragments ONCE per kernel ----
    uint32_t fB[4][8];
    {
        uint32_t bFOff = sbase + OFF_WF + (uint32_t)((n0 + brow) * SA) + bcolB;
        #pragma unroll
        for (int ks = 0; ks < 4; ++ks) {
            ldsm4(fB[ks][0], fB[ks][1], fB[ks][2], fB[ks][3], bFOff + ks * 32);
            ldsm4(fB[ks][4], fB[ks][5], fB[ks][6], fB[ks][7], bFOff + 16 * SA + ks * 32);
        }
    }

    // ---------------- Batch loop (persistent, 1 CTA/SM, 512 thr) ----------------
    for (int bb = blockIdx.x; bb < Bsz; bb += gridDim.x) {

        // ---- Stage A (bf16), 8B stores; prefetch next batch's A to L2 ----
        {
            const float4* A4 = reinterpret_cast<const float4*>(nb + (size_t)bb * Nn * Dd);
            #pragma unroll
            for (int it = 0; it < 8; ++it) {
                int idx = it * NTHREADS + t;
                int row = idx >> 4, d0 = (idx & 15) * 4;
                float4 v = A4[idx];
                *(uint2*)(smem + OFF_A + row * SA + d0 * 2) =
                    make_uint2(cvt2(v.x, v.y), cvt2(v.z, v.w));
            }
            int bnext = bb + gridDim.x;
            if (bnext < Bsz) {
                const char* pn = (const char*)(nb + (size_t)bnext * Nn * Dd);
                #pragma unroll
                for (int it = 0; it < 8; ++it)
                    asm volatile("prefetch.global.L2 [%0];"
                                 :: "l"(pn + (size_t)(it * NTHREADS + t) * 16));
            }
        }
        __syncthreads();

        // ---- E = A @ Wc (warp tile 16x32, K=64); bc folded into acc init ----
        float eacc[4][4];
        #pragma unroll
        for (int nt = 0; nt < 4; ++nt) {
            float b0 = sbc[nt * 8 + cpair], b1 = sbc[nt * 8 + cpair + 1];
            eacc[nt][0] = b0; eacc[nt][1] = b1; eacc[nt][2] = b0; eacc[nt][3] = b1;
        }
        {
            uint32_t aOff = sbase + OFF_A + (uint32_t)((emg * 16 + arow) * SA) + acolB;
            uint32_t bOff = sbase + OFF_WC + (uint32_t)(brow * SA) + bcolB;
            #pragma unroll
            for (int ks = 0; ks < 4; ++ks) {
                uint32_t p0, p1, p2, p3, q0, q1, q2, q3;
                ldsm4(p0, p1, p2, p3, bOff + ks * 32);
                ldsm4(q0, q1, q2, q3, bOff + 16 * SA + ks * 32);
                uint32_t a0, a1, a2, a3;
                ldsm4(a0, a1, a2, a3, aOff + ks * 32);
                mma_bf16(eacc[0], a0, a1, a2, a3, p0, p1);
                mma_bf16(eacc[1], a0, a1, a2, a3, p2, p3);
                mma_bf16(eacc[2], a0, a1, a2, a3, q0, q1);
                mma_bf16(eacc[3], a0, a1, a2, a3, q2, q3);
            }
        }
        // ---- E' = bf16(relu(E)) ----
        {
            int r = emg * 16 + rquad;
            #pragma unroll
            for (int nt = 0; nt < 4; ++nt) {
                int c = nt * 8 + cpair;
                *(uint32_t*)(smem + OFF_E + r * SE + c * 2) =
                    cvt2(fmaxf(eacc[nt][0], 0.f), fmaxf(eacc[nt][1], 0.f));
                *(uint32_t*)(smem + OFF_E + (r + 8) * SE + c * 2) =
                    cvt2(fmaxf(eacc[nt][2], 0.f), fmaxf(eacc[nt][3], 0.f));
            }
        }
        __syncthreads();

        // ---- Per 32-row sub-block: L GEMM -> ex2 -> F GEMM (B in regs) -> acc ----
        float sp[4][2], wp[4][2];
        #pragma unroll
        for (int nt = 0; nt < 4; ++nt) { sp[nt][0] = sp[nt][1] = wp[nt][0] = wp[nt][1] = 0.f; }

        #pragma unroll 1
        for (int sb = 0; sb < 2; ++sb) {
            const int m0h = mg * 64 + sb * 32;
            const uint32_t aLOff = sbase + OFF_E + (uint32_t)((m0h + arow) * SE) + acolB;
            const uint32_t bLOff = sbase + OFF_WA + (uint32_t)((n0 + brow) * SE) + bcolB;
            const uint32_t aFOff = sbase + OFF_A + (uint32_t)((m0h + arow) * SA) + acolB;

            // L' = E' @ (Wa2*log2e) (32x32, K=32)
            float lacc[2][4][4];
            #pragma unroll
            for (int mt = 0; mt < 2; ++mt)
                #pragma unroll
                for (int nt = 0; nt < 4; ++nt)
                    #pragma unroll
                    for (int i = 0; i < 4; ++i) lacc[mt][nt][i] = 0.f;
            #pragma unroll
            for (int ks = 0; ks < 2; ++ks) {
                uint32_t p0, p1, p2, p3, q0, q1, q2, q3;
                ldsm4(p0, p1, p2, p3, bLOff + ks * 32);
                ldsm4(q0, q1, q2, q3, bLOff + 16 * SE + ks * 32);
                #pragma unroll
                for (int mt = 0; mt < 2; ++mt) {
                    uint32_t a0, a1, a2, a3;
                    ldsm4(a0, a1, a2, a3, aLOff + mt * (16 * SE) + ks * 32);
                    mma_bf16(lacc[mt][0], a0, a1, a2, a3, p0, p1);
                    mma_bf16(lacc[mt][1], a0, a1, a2, a3, p2, p3);
                    mma_bf16(lacc[mt][2], a0, a1, a2, a3, q0, q1);
                    mma_bf16(lacc[mt][3], a0, a1, a2, a3, q2, q3);
                }
            }
            // u = 2^(L') — single MUFU each (|logit| < ~3.5: no max-subtraction)
            #pragma unroll
            for (int mt = 0; mt < 2; ++mt)
                #pragma unroll
                for (int nt = 0; nt < 4; ++nt)
                    #pragma unroll
                    for (int i = 0; i < 4; ++i) lacc[mt][nt][i] = ex2(lacc[mt][nt][i]);

            // F = A @ Wf + bf (32x32, K=64); bf folded into acc init; B in regs
            float facc[2][4][4];
            #pragma unroll
            for (int mt = 0; mt < 2; ++mt)
                #pragma unroll
                for (int nt = 0; nt < 4; ++nt) {
                    float b0 = sbfb[n0 + nt * 8 + cpair], b1 = sbfb[n0 + nt * 8 + cpair + 1];
                    facc[mt][nt][0] = b0; facc[mt][nt][1] = b1;
                    facc[mt][nt][2] = b0; facc[mt][nt][3] = b1;
                }
            #pragma unroll
            for (int ks = 0; ks < 4; ++ks) {
                #pragma unroll
                for (int mt = 0; mt < 2; ++mt) {
                    uint32_t a0, a1, a2, a3;
                    ldsm4(a0, a1, a2, a3, aFOff + mt * (16 * SA) + ks * 32);
                    mma_bf16(facc[mt][0], a0, a1, a2, a3, fB[ks][0], fB[ks][1]);
                    mma_bf16(facc[mt][1], a0, a1, a2, a3, fB[ks][2], fB[ks][3]);
                    mma_bf16(facc[mt][2], a0, a1, a2, a3, fB[ks][4], fB[ks][5]);
                    mma_bf16(facc[mt][3], a0, a1, a2, a3, fB[ks][6], fB[ks][7]);
                }
            }

            // weighted accumulate (u and F share identical fragment maps)
            #pragma unroll
            for (int nt = 0; nt < 4; ++nt) {
                #pragma unroll
                for (int mt = 0; mt < 2; ++mt) {
                    float u0 = lacc[mt][nt][0], u1 = lacc[mt][nt][1];
                    float u2 = lacc[mt][nt][2], u3 = lacc[mt][nt][3];
                    sp[nt][0] += u0 + u2;
                    sp[nt][1] += u1 + u3;
                    wp[nt][0] += u0 * fmaxf(facc[mt][nt][0], 0.f)
                               + u2 * fmaxf(facc[mt][nt][2], 0.f);
                    wp[nt][1] += u1 * fmaxf(facc[mt][nt][1], 0.f)
                               + u3 * fmaxf(facc[mt][nt][3], 0.f);
                }
            }
        }

        // ---- Row reduce: intra-warp shfl, then cross-mg (4 groups) via smem ----
        #pragma unroll
        for (int s = 4; s < 32; s <<= 1) {
            #pragma unroll
            for (int nt = 0; nt < 4; ++nt) {
                sp[nt][0] += __shfl_xor_sync(0xFFFFFFFFu, sp[nt][0], s);
                sp[nt][1] += __shfl_xor_sync(0xFFFFFFFFu, sp[nt][1], s);
                wp[nt][0] += __shfl_xor_sync(0xFFFFFFFFu, wp[nt][0], s);
                wp[nt][1] += __shfl_xor_sync(0xFFFFFFFFu, wp[nt][1], s);
            }
        }
        if (rquad == 0) {
            #pragma unroll
            for (int nt = 0; nt < 4; ++nt) {
                int c = n0 + nt * 8 + cpair;
                *(float2*)(sRedS + mg * 132 + c) = make_float2(sp[nt][0], sp[nt][1]);
                *(float2*)(sRedW + mg * 132 + c) = make_float2(wp[nt][0], wp[nt][1]);
            }
        }
        __syncthreads();

        if (t < LAT) {
            float S = 0.f, W = 0.f;
            #pragma unroll
            for (int g = 0; g < 4; ++g) { S += sRedS[g * 132 + t]; W += sRedW[g * 132 + t]; }
            sAgg[t] = W / S;
        }
        __syncthreads();

        // ---- out[bb] = relu(agg @ Wl + bl) ----
        {
            const int q = t >> 7, k = t & 127;     // q in {0..3}: 32 j each
            float p4 = 0.f;
            #pragma unroll 8
            for (int j = 0; j < 32; ++j) {
                int jj = q * 32 + j;
                p4 = fmaf(sAgg[jj], __ldg(&Wl[jj * LAT + k]), p4);
            }
            sP4[q * 132 + k] = p4;
        }
        __syncthreads();
        if (t < LAT) {
            float acc = __ldg(&bl[t]);
            #pragma unroll
            for (int q = 0; q < 4; ++q) acc += sP4[q * 132 + t];
            out[(size_t)bb * LAT + t] = fmaxf(acc, 0.f);
        }
        __syncthreads();   // A/E'/sRed reuse next batch
    }
}

extern "C" void kernel_launch(void* const* d_in, const int* in_sizes, int n_in,
                              void* d_out, int out_size) {
    // metadata order: local_data, neighbor_data, Wc, bc, Wf, bf, Wa, ba, Wl, bl
    // local_data and ba provably unused (softmax shift-invariance over n).
    const float* nb = (const float*)d_in[1];
    const float* Wc = (const float*)d_in[2];
    const float* bc = (const float*)d_in[3];
    const float* Wf = (const float*)d_in[4];
    const float* bf = (const float*)d_in[5];
    const float* Wa = (const float*)d_in[6];
    const float* Wl = (const float*)d_in[8];
    const float* bl = (const float*)d_in[9];
    float* out = (float*)d_out;

    int sms = 152;
    cudaDeviceGetAttribute(&sms, cudaDevAttrMultiProcessorCount, 0);
    if (sms < 1) sms = 152;
    int grid = sms;
    if (grid > Bsz) grid = Bsz;

    cudaFuncSetAttribute(arm_mma12_kernel,
                         cudaFuncAttributeMaxDynamicSharedMemorySize, (int)SMEM_TOTAL);
    arm_mma12_kernel<<<grid, NTHREADS, SMEM_TOTAL>>>(nb, Wc, bc, Wf, bf, Wa, Wl, bl, out);
}